// round 16
// baseline (speedup 1.0000x reference)
#include <cuda_runtime.h>
#include <cuda_bf16.h>
#include <math.h>

// Problem constants
#define BB 64
#define TT 512
#define II 1024
#define HH 1024
#define BH (BB * HH)         // 65536
#define TH ((size_t)TT * HH) // 524288

#define GRP_BLOCKS 32        // blocks per independent b-group barrier

// Scratch: preactivation xp[t][b][h] = x@W_ih^T + b_ih + b_hh  (128 MB)
__device__ float g_xp[(size_t)TT * BB * HH];

// Per-group grid-barrier state (4 groups, each on its own 128B line).
// gen is MONOTONIC across graph replays; count is reset by the releaser
// before the fenced gen bump, so count==0 at every kernel entry.
__device__ unsigned g_bar_count4[4 * 32];
__device__ unsigned g_bar_gen4[4 * 32];

// ---------------------------------------------------------------------------
// f32x2 helpers (Blackwell packed fp32 FMA: 2 MACs per instruction)
// ---------------------------------------------------------------------------
__device__ __forceinline__ unsigned long long dup2(float v) {
    unsigned long long r;
    asm("mov.b64 %0, {%1, %1};" : "=l"(r) : "r"(__float_as_uint(v)));
    return r;
}
__device__ __forceinline__ void ffma2(unsigned long long& acc,
                                      unsigned long long a,
                                      unsigned long long b) {
    asm("fma.rn.f32x2 %0, %1, %2, %0;" : "+l"(acc) : "l"(a), "l"(b));
}
__device__ __forceinline__ void unpack2(unsigned long long v, float& lo, float& hi) {
    unsigned int l, h;
    asm("mov.b64 {%0, %1}, %2;" : "=r"(l), "=r"(h) : "l"(v));
    lo = __uint_as_float(l);
    hi = __uint_as_float(h);
}
__device__ __forceinline__ unsigned ld_acq(const unsigned* p) {
    unsigned v;
    asm volatile("ld.acquire.gpu.u32 %0, [%1];" : "=r"(v) : "l"(p));
    return v;
}

// ---------------------------------------------------------------------------
// Phase 1: xp GEMM.  C[r][n] = sum_i X[r][i] * W_ih[n][i],  r = b*T + t.
// (unchanged — known good)
// ---------------------------------------------------------------------------
__global__ __launch_bounds__(256) void xp_gemm_kernel(
    const float* __restrict__ X,     // [B*T, I]
    const float* __restrict__ Wih,   // [H, I]
    const float* __restrict__ bih,   // [H]
    const float* __restrict__ bhh)   // [H]
{
    __shared__ float As[2][64][32];
    __shared__ float Ws[2][32][34];

    const int tid = threadIdx.x;
    const int r0 = blockIdx.y * 64;
    const int n0 = blockIdx.x * 32;

    float4 ra[2], rw;

    auto loadA = [&](int kt) {
#pragma unroll
        for (int i = 0; i < 2; i++) {
            int idx = tid + 256 * i;
            int row = idx >> 3, kq = idx & 7;
            ra[i] = *(const float4*)(X + (size_t)(r0 + row) * II + kt * 32 + kq * 4);
        }
    };
    auto loadW = [&](int kt) {
        int row = tid >> 3, kq = tid & 7;
        rw = *(const float4*)(Wih + (size_t)(n0 + row) * II + kt * 32 + kq * 4);
    };
    auto storeT = [&](int buf) {
#pragma unroll
        for (int i = 0; i < 2; i++) {
            int idx = tid + 256 * i;
            int row = idx >> 3, kq = idx & 7;
            *(float4*)&As[buf][row][kq * 4] = ra[i];
        }
        int row = tid >> 3, kq = tid & 7;
        Ws[buf][kq * 4 + 0][row] = rw.x;
        Ws[buf][kq * 4 + 1][row] = rw.y;
        Ws[buf][kq * 4 + 2][row] = rw.z;
        Ws[buf][kq * 4 + 3][row] = rw.w;
    };

    loadA(0);
    loadW(0);
    storeT(0);
    __syncthreads();

    const int tx = tid & 15;
    const int ty = tid >> 4;
    const int mm = ty * 4;
    const int nn = tx * 2;

    unsigned long long acc0 = 0ULL, acc1 = 0ULL, acc2 = 0ULL, acc3 = 0ULL;

    const int NT = II / 32;
    for (int kt = 0; kt < NT; kt++) {
        const int buf = kt & 1;
        if (kt + 1 < NT) { loadA(kt + 1); loadW(kt + 1); }
#pragma unroll
        for (int k4 = 0; k4 < 32; k4 += 4) {
            float4 a0 = *(const float4*)&As[buf][mm + 0][k4];
            float4 a1 = *(const float4*)&As[buf][mm + 1][k4];
            float4 a2 = *(const float4*)&As[buf][mm + 2][k4];
            float4 a3 = *(const float4*)&As[buf][mm + 3][k4];
#pragma unroll
            for (int u = 0; u < 4; u++) {
                unsigned long long pb =
                    *(const unsigned long long*)&Ws[buf][k4 + u][nn];
                ffma2(acc0, dup2((&a0.x)[u]), pb);
                ffma2(acc1, dup2((&a1.x)[u]), pb);
                ffma2(acc2, dup2((&a2.x)[u]), pb);
                ffma2(acc3, dup2((&a3.x)[u]), pb);
            }
        }
        if (kt + 1 < NT) {
            storeT(buf ^ 1);
            __syncthreads();
        }
    }

    const int n = n0 + nn;
    const float bias0 = bih[n] + bhh[n];
    const float bias1 = bih[n + 1] + bhh[n + 1];

    unsigned long long accs[4] = {acc0, acc1, acc2, acc3};
#pragma unroll
    for (int j = 0; j < 4; j++) {
        float c0, c1;
        unpack2(accs[j], c0, c1);
        int r = r0 + mm + j;
        int b = r >> 9;
        int t = r & (TT - 1);
        float* dst = g_xp + (size_t)t * BH + (size_t)b * HH + n;
        dst[0] = c0 + bias0;
        dst[1] = c1 + bias1;
    }
}

// ---------------------------------------------------------------------------
// Phase 2: persistent recurrence kernel.
// Grid 128 blocks = 4 b-groups (BM=16) x 32 n-tiles (BN=32), 512 threads.
// W_hh slice resident in smem (k-major [1024][32] = 128 KB), staged once,
// conflict-free. Per step: cooperative conflict-free h staging, 16 warps =
// 8 k-groups x 2 m-halves, microtile 2m x 4n via f32x2 (issue load == fma
// floor), padded split-K partials, fixed-order combine + tanh, write h into
// out[b][t][h], then a per-b-group (32-block) grid barrier.
// ---------------------------------------------------------------------------
#define HS_STRIDE 20
#define PS_STRIDE 36                               // padded m-row stride
#define PS_G      (16 * PS_STRIDE)                 // 576 floats per k-group
#define SMEM_WS   (1024 * 32)                      // 32768 floats
#define SMEM_HS   (1024 * HS_STRIDE)               // 20480 floats
#define SMEM_PS   (8 * PS_G)                       // 4608 floats
#define SMEM_FLOATS (SMEM_WS + SMEM_HS + SMEM_PS)  // 57856
#define SMEM_BYTES  (SMEM_FLOATS * 4)              // 231424 B (< 232448 max)

__global__ __launch_bounds__(512, 1) void rnn_persistent_kernel(
    const float* __restrict__ h0,    // [B, H]
    const float* __restrict__ Whh,   // [H, H]
    float* __restrict__ out)         // [B, T, H]
{
    extern __shared__ float smem[];
    float* ws = smem;                      // [k][32]
    float* hs = smem + SMEM_WS;            // [k][HS_STRIDE], b in [0,16)
    float* ps = smem + SMEM_WS + SMEM_HS;  // [8][16][PS_STRIDE]

    const int tid = threadIdx.x;
    const int n0 = blockIdx.x * 32;   // 32 n-tiles
    const int grp = blockIdx.y;       // 4 independent b-groups
    const int m0 = grp * 16;

    unsigned* bar_cnt = &g_bar_count4[grp * 32];
    unsigned* bar_gen = &g_bar_gen4[grp * 32];

    // Snapshot this group's barrier generation BEFORE any arrive.
    unsigned gen0 = 0;
    if (tid == 0) gen0 = ld_acq(bar_gen);

    // ---- Stage W_hh slice once: ws[k*32 + n] = W_hh[n0+n][k] ----
    // Warp pattern: n = lane (all 32 banks), f4 constant -> conflict-free STS.
#pragma unroll
    for (int i = 0; i < 16; i++) {
        int idx = tid + 512 * i;          // 0..8191
        int n = idx & 31;
        int f4 = idx >> 5;                // 0..255
        float4 v = *(const float4*)(Whh + (size_t)(n0 + n) * HH + f4 * 4);
        ws[(f4 * 4 + 0) * 32 + n] = v.x;
        ws[(f4 * 4 + 1) * 32 + n] = v.y;
        ws[(f4 * 4 + 2) * 32 + n] = v.z;
        ws[(f4 * 4 + 3) * 32 + n] = v.w;
    }
    __syncthreads();

    const int wid = tid >> 5;
    const int lane = tid & 31;
    const int g = wid >> 1;           // k-group (0..7)
    const int half = wid & 1;         // m-half (0..1)
    const int k0 = g * 128;
    const int nq = lane & 7;          // n quad: n = nq*4 .. nq*4+3
    const int mq = lane >> 3;         // 0..3
    const int mbase = half * 8 + mq * 2;   // m rows mbase, mbase+1

    // Combine mapping: one output per thread.
    const int cm = tid >> 5;          // local b (0..15)
    const int cn = tid & 31;          // local n (0..31)

    for (int t = 0; t < TT; t++) {
        const float* hsrc;
        size_t hstride;
        if (t == 0) { hsrc = h0 + (size_t)m0 * HH;                         hstride = HH; }
        else        { hsrc = out + (size_t)m0 * TH + (size_t)(t - 1) * HH; hstride = TH; }

        // Prefetch this thread's xp value (DRAM) — consumed after compute.
        float xv = g_xp[(size_t)t * BH + (size_t)(m0 + cm) * HH + n0 + cn];

        // ---- Cooperative conflict-free h staging: hs[k*20 + b] ----
        // Warp pattern: lanes 0-15 -> b=0..15 @ f4=c, lanes 16-31 -> b=0..15
        // @ f4=c+1. STS words 80c+20j+b and 80c+80+20j+b cover complementary
        // 16-bank sets -> conflict-free.
#pragma unroll
        for (int i = 0; i < 8; i++) {
            int idx = tid + 512 * i;      // 0..4095
            int b = idx & 15;
            int f4 = idx >> 4;            // 0..255
            float4 v = *(const float4*)(hsrc + (size_t)b * hstride + f4 * 4);
            hs[(f4 * 4 + 0) * HS_STRIDE + b] = v.x;
            hs[(f4 * 4 + 1) * HS_STRIDE + b] = v.y;
            hs[(f4 * 4 + 2) * HS_STRIDE + b] = v.z;
            hs[(f4 * 4 + 3) * HS_STRIDE + b] = v.w;
        }
        __syncthreads();

        // ---- Compute: split-K, microtile 2m x 4n per lane ----
        unsigned long long acc00 = 0ULL, acc01 = 0ULL;
        unsigned long long acc10 = 0ULL, acc11 = 0ULL;

#pragma unroll 8
        for (int k = k0; k < k0 + 128; k++) {
            float2 av = *(const float2*)&hs[k * HS_STRIDE + mbase];
            ulonglong2 bv = *(const ulonglong2*)&ws[k * 32 + nq * 4];
            unsigned long long a0 = dup2(av.x);
            unsigned long long a1 = dup2(av.y);
            ffma2(acc00, a0, bv.x);
            ffma2(acc01, a0, bv.y);
            ffma2(acc10, a1, bv.x);
            ffma2(acc11, a1, bv.y);
        }

        // ---- Store partials (padded layout, ~2-way max conflict) ----
        {
            ulonglong2 p0; p0.x = acc00; p0.y = acc01;
            ulonglong2 p1; p1.x = acc10; p1.y = acc11;
            *(ulonglong2*)&ps[g * PS_G + (mbase + 0) * PS_STRIDE + nq * 4] = p0;
            *(ulonglong2*)&ps[g * PS_G + (mbase + 1) * PS_STRIDE + nq * 4] = p1;
        }
        __syncthreads();

        // ---- Combine (fixed order) + xp + tanh + write h into out ----
        {
            float s = 0.0f;
#pragma unroll
            for (int gg = 0; gg < 8; gg++)
                s += ps[gg * PS_G + cm * PS_STRIDE + cn];
            float r = tanhf(s + xv);
            out[(size_t)(m0 + cm) * TH + (size_t)t * HH + n0 + cn] = r;
        }

        // ---- Per-group grid barrier (32 blocks) ----
        __syncthreads();   // ps reads done; out-writes issued by all threads
        if (tid == 0) {
            __threadfence();   // release this block's out-writes (gpu scope)
            unsigned old = atomicAdd(bar_cnt, 1);
            unsigned target = gen0 + (unsigned)(t + 1);
            if (old == GRP_BLOCKS - 1) {
                atomicExch(bar_cnt, 0);
                __threadfence();
                atomicAdd(bar_gen, 1);   // reaches target
            } else {
                while ((int)(ld_acq(bar_gen) - target) < 0) {
                    __nanosleep(32);
                }
            }
        }
        __syncthreads();
    }
}

// ---------------------------------------------------------------------------
// Launch
// ---------------------------------------------------------------------------
extern "C" void kernel_launch(void* const* d_in, const int* in_sizes, int n_in,
                              void* d_out, int out_size) {
    const float* x    = (const float*)d_in[0];  // [B, T, I]
    const float* h0   = (const float*)d_in[1];  // [1, B, H]
    const float* W_ih = (const float*)d_in[2];  // [H, I]
    const float* b_ih = (const float*)d_in[3];  // [H]
    const float* W_hh = (const float*)d_in[4];  // [H, H]
    const float* b_hh = (const float*)d_in[5];  // [H]
    float* out = (float*)d_out;                 // [B, T, H]

    // Phase 1: input projection for all timesteps (biases folded in)
    dim3 g1(HH / 32, (BB * TT) / 64);  // (32, 512)
    xp_gemm_kernel<<<g1, 256>>>(x, W_ih, b_ih, b_hh);

    // Phase 2: persistent recurrence (single kernel, per-b-group barriers)
    cudaFuncSetAttribute(rnn_persistent_kernel,
                         cudaFuncAttributeMaxDynamicSharedMemorySize, SMEM_BYTES);
    dim3 g2(32, 4);  // 128 blocks, all co-resident on 148 SMs
    rnn_persistent_kernel<<<g2, 512, SMEM_BYTES>>>(h0, W_hh, out);
}

// round 17
// speedup vs baseline: 1.3271x; 1.3271x over previous
#include <cuda_runtime.h>
#include <cuda_bf16.h>
#include <math.h>

// Problem constants
#define BB 64
#define TT 512
#define II 1024
#define HH 1024
#define BH (BB * HH)         // 65536
#define TH ((size_t)TT * HH) // 524288

#define NBLOCKS 128

// Scratch: preactivation xp[t][b][h] = x@W_ih^T + b_ih + b_hh  (128 MB)
__device__ float g_xp[(size_t)TT * BB * HH];

// Grid-barrier state (monotonic gen across graph replays; count reset by
// releaser before the fenced gen bump, so count==0 at every kernel entry).
__device__ unsigned g_bar_count;
__device__ unsigned g_bar_gen;

// ---------------------------------------------------------------------------
// f32x2 helpers (Blackwell packed fp32 FMA: 2 MACs per instruction)
// ---------------------------------------------------------------------------
__device__ __forceinline__ unsigned long long dup2(float v) {
    unsigned long long r;
    asm("mov.b64 %0, {%1, %1};" : "=l"(r) : "r"(__float_as_uint(v)));
    return r;
}
__device__ __forceinline__ void ffma2(unsigned long long& acc,
                                      unsigned long long a,
                                      unsigned long long b) {
    asm("fma.rn.f32x2 %0, %1, %2, %0;" : "+l"(acc) : "l"(a), "l"(b));
}
__device__ __forceinline__ void unpack2(unsigned long long v, float& lo, float& hi) {
    unsigned int l, h;
    asm("mov.b64 {%0, %1}, %2;" : "=r"(l), "=r"(h) : "l"(v));
    lo = __uint_as_float(l);
    hi = __uint_as_float(h);
}
__device__ __forceinline__ unsigned ld_acq(const unsigned* p) {
    unsigned v;
    asm volatile("ld.acquire.gpu.u32 %0, [%1];" : "=r"(v) : "l"(p));
    return v;
}

// ---------------------------------------------------------------------------
// Phase 1: xp GEMM.  C[r][n] = sum_i X[r][i] * W_ih[n][i],  r = b*T + t.
// (unchanged — known good)
// ---------------------------------------------------------------------------
__global__ __launch_bounds__(256) void xp_gemm_kernel(
    const float* __restrict__ X,     // [B*T, I]
    const float* __restrict__ Wih,   // [H, I]
    const float* __restrict__ bih,   // [H]
    const float* __restrict__ bhh)   // [H]
{
    __shared__ float As[2][64][32];
    __shared__ float Ws[2][32][34];

    const int tid = threadIdx.x;
    const int r0 = blockIdx.y * 64;
    const int n0 = blockIdx.x * 32;

    float4 ra[2], rw;

    auto loadA = [&](int kt) {
#pragma unroll
        for (int i = 0; i < 2; i++) {
            int idx = tid + 256 * i;
            int row = idx >> 3, kq = idx & 7;
            ra[i] = *(const float4*)(X + (size_t)(r0 + row) * II + kt * 32 + kq * 4);
        }
    };
    auto loadW = [&](int kt) {
        int row = tid >> 3, kq = tid & 7;
        rw = *(const float4*)(Wih + (size_t)(n0 + row) * II + kt * 32 + kq * 4);
    };
    auto storeT = [&](int buf) {
#pragma unroll
        for (int i = 0; i < 2; i++) {
            int idx = tid + 256 * i;
            int row = idx >> 3, kq = idx & 7;
            *(float4*)&As[buf][row][kq * 4] = ra[i];
        }
        int row = tid >> 3, kq = tid & 7;
        Ws[buf][kq * 4 + 0][row] = rw.x;
        Ws[buf][kq * 4 + 1][row] = rw.y;
        Ws[buf][kq * 4 + 2][row] = rw.z;
        Ws[buf][kq * 4 + 3][row] = rw.w;
    };

    loadA(0);
    loadW(0);
    storeT(0);
    __syncthreads();

    const int tx = tid & 15;
    const int ty = tid >> 4;
    const int mm = ty * 4;
    const int nn = tx * 2;

    unsigned long long acc0 = 0ULL, acc1 = 0ULL, acc2 = 0ULL, acc3 = 0ULL;

    const int NT = II / 32;
    for (int kt = 0; kt < NT; kt++) {
        const int buf = kt & 1;
        if (kt + 1 < NT) { loadA(kt + 1); loadW(kt + 1); }
#pragma unroll
        for (int k4 = 0; k4 < 32; k4 += 4) {
            float4 a0 = *(const float4*)&As[buf][mm + 0][k4];
            float4 a1 = *(const float4*)&As[buf][mm + 1][k4];
            float4 a2 = *(const float4*)&As[buf][mm + 2][k4];
            float4 a3 = *(const float4*)&As[buf][mm + 3][k4];
#pragma unroll
            for (int u = 0; u < 4; u++) {
                unsigned long long pb =
                    *(const unsigned long long*)&Ws[buf][k4 + u][nn];
                ffma2(acc0, dup2((&a0.x)[u]), pb);
                ffma2(acc1, dup2((&a1.x)[u]), pb);
                ffma2(acc2, dup2((&a2.x)[u]), pb);
                ffma2(acc3, dup2((&a3.x)[u]), pb);
            }
        }
        if (kt + 1 < NT) {
            storeT(buf ^ 1);
            __syncthreads();
        }
    }

    const int n = n0 + nn;
    const float bias0 = bih[n] + bhh[n];
    const float bias1 = bih[n + 1] + bhh[n + 1];

    unsigned long long accs[4] = {acc0, acc1, acc2, acc3};
#pragma unroll
    for (int j = 0; j < 4; j++) {
        float c0, c1;
        unpack2(accs[j], c0, c1);
        int r = r0 + mm + j;
        int b = r >> 9;
        int t = r & (TT - 1);
        float* dst = g_xp + (size_t)t * BH + (size_t)b * HH + n;
        dst[0] = c0 + bias0;
        dst[1] = c1 + bias1;
    }
}

// ---------------------------------------------------------------------------
// Phase 2: persistent recurrence kernel (R14 skeleton, conflict-free layouts).
// Grid 128 blocks = 4 b-tiles (BM=16) x 32 n-tiles (BN=32), 256 threads.
// W_hh slice in smem k-major [1024][32] (conflict-free staging, done once).
// h slice in smem ROW-major hs2[b][k] stride 1028 -> staging is a straight
// contiguous copy (coalesced LDG.128 + consecutive STS.128, zero conflicts).
// Compute: 8-way k-split (128 k per warp), microtile 4m x 4n per lane with
// m interleaved (m = mq + 4i) so a-row LDS.128s are bank-conflict-free.
// Fixed-order split-K combine in smem, tanh, write h into out[b][t][h],
// global 128-block grid barrier (R14's, known good).
// ---------------------------------------------------------------------------
#define H2_STRIDE 1028                             // floats per b row (pad 4)
#define PS_STRIDE 36
#define PS_G      (16 * PS_STRIDE)                 // 576 floats per k-group
#define SMEM_WS   (1024 * 32)                      // 32768 floats
#define SMEM_HS   (16 * H2_STRIDE)                 // 16448 floats
#define SMEM_PS   (8 * PS_G)                       // 4608 floats
#define SMEM_FLOATS (SMEM_WS + SMEM_HS + SMEM_PS)  // 53824
#define SMEM_BYTES  (SMEM_FLOATS * 4)              // 215296 B

__global__ __launch_bounds__(256, 1) void rnn_persistent_kernel(
    const float* __restrict__ h0,    // [B, H]
    const float* __restrict__ Whh,   // [H, H]
    float* __restrict__ out)         // [B, T, H]
{
    extern __shared__ float smem[];
    float* ws  = smem;                      // [k][32]
    float* hs2 = smem + SMEM_WS;            // [b][H2_STRIDE]
    float* ps  = smem + SMEM_WS + SMEM_HS;  // [8][16][PS_STRIDE]

    const int tid = threadIdx.x;
    const int n0 = blockIdx.x * 32;   // 32 n-tiles
    const int m0 = blockIdx.y * 16;   // 4 b-tiles

    // Snapshot barrier generation BEFORE any arrive.
    unsigned gen0 = 0;
    if (tid == 0) gen0 = ld_acq(&g_bar_gen);

    // ---- Stage W_hh slice once: ws[k*32 + n] = W_hh[n0+n][k] ----
    // Lane pattern: n = lane -> STS word stride 1 -> conflict-free.
#pragma unroll
    for (int i = 0; i < 32; i++) {
        int idx = tid + 256 * i;          // 0..8191
        int n = idx & 31;
        int f4 = idx >> 5;                // 0..255
        float4 v = *(const float4*)(Whh + (size_t)(n0 + n) * HH + f4 * 4);
        ws[(f4 * 4 + 0) * 32 + n] = v.x;
        ws[(f4 * 4 + 1) * 32 + n] = v.y;
        ws[(f4 * 4 + 2) * 32 + n] = v.z;
        ws[(f4 * 4 + 3) * 32 + n] = v.w;
    }
    __syncthreads();

    const int g = tid >> 5;           // warp = k-group (0..7)
    const int lane = tid & 31;
    const int mq = lane >> 3;         // 0..3 ; m rows = mq + 4i, i=0..3
    const int nq = lane & 7;          // 0..7 ; n = nq*4 .. nq*4+3
    const int k0 = g * 128;

    // Combine mapping: 2 outputs (float2) per thread.
    const int co = tid * 2;           // 0..510
    const int cm = co >> 5;           // local b (0..15)
    const int cn = co & 31;           // local n (even)

    for (int t = 0; t < TT; t++) {
        const float* hsrc;
        size_t hstride;
        if (t == 0) { hsrc = h0 + (size_t)m0 * HH;                         hstride = HH; }
        else        { hsrc = out + (size_t)m0 * TH + (size_t)(t - 1) * HH; hstride = TH; }

        // Prefetch this thread's xp float2 (DRAM) — consumed in the epilogue.
        float2 xv = *(const float2*)(g_xp + (size_t)t * BH +
                                     (size_t)(m0 + cm) * HH + n0 + cn);

        // ---- h staging: straight copy hs2[b][k] = hprev[m0+b][k] ----
        // Warp: b fixed, f4 = fbase + lane -> coalesced LDG.128 (full lines)
        // and consecutive STS.128 (conflict-free).
#pragma unroll
        for (int i = 0; i < 16; i++) {
            int idx = tid + 256 * i;      // 0..4095
            int b = idx >> 8;             // 0..15
            int f4 = idx & 255;           // 0..255
            float4 v = *(const float4*)(hsrc + (size_t)b * hstride + f4 * 4);
            *(float4*)&hs2[b * H2_STRIDE + f4 * 4] = v;
        }
        __syncthreads();

        // ---- Compute: split-K, microtile 4m x 4n (m interleaved) ----
        unsigned long long acc[8];
#pragma unroll
        for (int i = 0; i < 8; i++) acc[i] = 0ULL;

#pragma unroll 8
        for (int k4 = 0; k4 < 32; k4++) {
            const int k = k0 + k4 * 4;
            // a[i] = 4 consecutive k of row (mq + 4i); address stride between
            // the 4 unique lane-addresses is 4*1028 words = 16 mod 32... per
            // instruction i, addresses differ by 1028 (=4 mod 32) across mq
            // -> 16 distinct banks, conflict-free, 8-lane broadcast.
            float4 a0 = *(const float4*)&hs2[(mq + 0)  * H2_STRIDE + k];
            float4 a1 = *(const float4*)&hs2[(mq + 4)  * H2_STRIDE + k];
            float4 a2 = *(const float4*)&hs2[(mq + 8)  * H2_STRIDE + k];
            float4 a3 = *(const float4*)&hs2[(mq + 12) * H2_STRIDE + k];
            ulonglong2 b0 = *(const ulonglong2*)&ws[(k + 0) * 32 + nq * 4];
            ulonglong2 b1 = *(const ulonglong2*)&ws[(k + 1) * 32 + nq * 4];
            ulonglong2 b2 = *(const ulonglong2*)&ws[(k + 2) * 32 + nq * 4];
            ulonglong2 b3 = *(const ulonglong2*)&ws[(k + 3) * 32 + nq * 4];
#pragma unroll
            for (int kk = 0; kk < 4; kk++) {
                ulonglong2 bv = (kk == 0) ? b0 : (kk == 1) ? b1
                              : (kk == 2) ? b2 : b3;
                unsigned long long ad;
                ad = dup2((&a0.x)[kk]); ffma2(acc[0], ad, bv.x); ffma2(acc[1], ad, bv.y);
                ad = dup2((&a1.x)[kk]); ffma2(acc[2], ad, bv.x); ffma2(acc[3], ad, bv.y);
                ad = dup2((&a2.x)[kk]); ffma2(acc[4], ad, bv.x); ffma2(acc[5], ad, bv.y);
                ad = dup2((&a3.x)[kk]); ffma2(acc[6], ad, bv.x); ffma2(acc[7], ad, bv.y);
            }
        }

        // ---- Store partials: ps[g][m][n], m = mq + 4i ----
#pragma unroll
        for (int i = 0; i < 4; i++) {
            int m = mq + 4 * i;
            ulonglong2 p;
            p.x = acc[2 * i + 0];
            p.y = acc[2 * i + 1];
            *(ulonglong2*)&ps[g * PS_G + m * PS_STRIDE + nq * 4] = p;
        }
        __syncthreads();

        // ---- Combine (fixed order) + xp + tanh + write h into out ----
        {
            float s0 = 0.0f, s1 = 0.0f;
#pragma unroll
            for (int gg = 0; gg < 8; gg++) {
                float2 p = *(const float2*)&ps[gg * PS_G + cm * PS_STRIDE + cn];
                s0 += p.x;
                s1 += p.y;
            }
            float r0 = tanhf(s0 + xv.x);
            float r1 = tanhf(s1 + xv.y);
            float* op = out + (size_t)(m0 + cm) * TH + (size_t)t * HH + n0 + cn;
            op[0] = r0;
            op[1] = r1;
        }

        // ---- Grid barrier: all h_t writes visible before any step t+1 read ----
        __syncthreads();   // ps reads done; out-writes issued by all threads
        if (tid == 0) {
            __threadfence();   // release this block's out-writes (gpu scope)
            unsigned old = atomicAdd(&g_bar_count, 1);
            unsigned target = gen0 + (unsigned)(t + 1);
            if (old == NBLOCKS - 1) {
                atomicExch(&g_bar_count, 0);
                __threadfence();
                atomicAdd(&g_bar_gen, 1);   // reaches target
            } else {
                while ((int)(ld_acq(&g_bar_gen) - target) < 0) {
                    __nanosleep(32);
                }
            }
        }
        __syncthreads();
    }
}

// ---------------------------------------------------------------------------
// Launch
// ---------------------------------------------------------------------------
extern "C" void kernel_launch(void* const* d_in, const int* in_sizes, int n_in,
                              void* d_out, int out_size) {
    const float* x    = (const float*)d_in[0];  // [B, T, I]
    const float* h0   = (const float*)d_in[1];  // [1, B, H]
    const float* W_ih = (const float*)d_in[2];  // [H, I]
    const float* b_ih = (const float*)d_in[3];  // [H]
    const float* W_hh = (const float*)d_in[4];  // [H, H]
    const float* b_hh = (const float*)d_in[5];  // [H]
    float* out = (float*)d_out;                 // [B, T, H]

    // Phase 1: input projection for all timesteps (biases folded in)
    dim3 g1(HH / 32, (BB * TT) / 64);  // (32, 512)
    xp_gemm_kernel<<<g1, 256>>>(x, W_ih, b_ih, b_hh);

    // Phase 2: persistent recurrence (single kernel, internal grid barriers)
    cudaFuncSetAttribute(rnn_persistent_kernel,
                         cudaFuncAttributeMaxDynamicSharedMemorySize, SMEM_BYTES);
    dim3 g2(32, 4);  // 128 blocks, all co-resident on 148 SMs
    rnn_persistent_kernel<<<g2, 256, SMEM_BYTES>>>(h0, W_hh, out);
}